// round 2
// baseline (speedup 1.0000x reference)
#include <cuda_runtime.h>
#include <math.h>

#define DM     512
#define BATCH  256
#define WIN    256
#define ENC    55
#define LATENT 128
#define KC     32
#define SH_STRIDE 68
#define SW_STRIDE 52

// Hidden-state history: slot t in [0, WIN], layout [t][b][j]
__device__ float g_hs[(WIN + 1) * BATCH * DM];

// ---------------------------------------------------------------------------
// h0 = tanh(z @ h_proj_w.T + h_proj_b)   (z: [256,128], W: [512,128])
// one block per batch row, 512 threads (one per output unit)
// ---------------------------------------------------------------------------
__global__ void h0_kernel(const float* __restrict__ z,
                          const float* __restrict__ w,
                          const float* __restrict__ bias) {
    __shared__ float zs[LATENT];
    const int b = blockIdx.x;
    const int j = threadIdx.x;
    if (threadIdx.x < LATENT) zs[threadIdx.x] = z[b * LATENT + threadIdx.x];
    __syncthreads();
    float acc = 0.f;
    const float4* wr = reinterpret_cast<const float4*>(w + (size_t)j * LATENT);
#pragma unroll
    for (int k4 = 0; k4 < LATENT / 4; k4++) {
        float4 w4 = __ldg(&wr[k4]);
        acc += zs[4 * k4 + 0] * w4.x + zs[4 * k4 + 1] * w4.y
             + zs[4 * k4 + 2] * w4.z + zs[4 * k4 + 3] * w4.w;
    }
    g_hs[(size_t)b * DM + j] = tanhf(acc + bias[j]);
}

// ---------------------------------------------------------------------------
// One GRU step: gh = h_t @ w_hh.T + b_hh; gates; h_{t+1}
// Grid: (DM/16 unit tiles, BATCH/64 batch tiles) = 32 x 4 = 128 CTAs, 128 thr.
// Thread tile: 4 batch x 2 units x 3 gates = 24 accumulators.
// ---------------------------------------------------------------------------
__global__ void __launch_bounds__(128)
step_kernel(const float* __restrict__ w_hh,
            const float* __restrict__ b_ih,
            const float* __restrict__ b_hh,
            int t) {
    __shared__ float shT[KC][SH_STRIDE];  // [kk][batch row 0..63] (transposed)
    __shared__ float swT[KC][SW_STRIDE];  // [kk][col 0..47] cols: 16r,16z,16n

    const int u0 = blockIdx.x * 16;   // unit tile base
    const int b0 = blockIdx.y * 64;   // batch tile base
    const int tid = threadIdx.x;
    const int tb = tid & 15;          // batch group: rows b0 + 4*tb .. +3
    const int tu = tid >> 4;          // unit group (0..7): units u0 + 2*tu..+1

    const float* __restrict__ hprev = g_hs + (size_t)t * (BATCH * DM);
    float* __restrict__ hnext = g_hs + (size_t)(t + 1) * (BATCH * DM);

    float accr[4][2] = {}, accz[4][2] = {}, accn[4][2] = {};

    for (int k0 = 0; k0 < DM; k0 += KC) {
        // Stage h tile (64 rows x 32 k) transposed into shT
#pragma unroll
        for (int p = 0; p < 4; p++) {
            int idx = tid + 128 * p;          // 0..511 (512 float4)
            int row = idx >> 3;               // 0..63
            int c4  = (idx & 7) * 4;          // 0,4,...,28
            float4 v = *reinterpret_cast<const float4*>(
                &hprev[(size_t)(b0 + row) * DM + k0 + c4]);
            shT[c4 + 0][row] = v.x;
            shT[c4 + 1][row] = v.y;
            shT[c4 + 2][row] = v.z;
            shT[c4 + 3][row] = v.w;
        }
        // Stage weight tile (48 rows x 32 k) transposed into swT
#pragma unroll
        for (int p = 0; p < 3; p++) {
            int idx = tid + 128 * p;          // 0..383 (384 float4)
            int lr  = idx >> 3;               // 0..47
            int c4  = (idx & 7) * 4;
            int g   = lr >> 4;                // gate 0..2
            int uu  = lr & 15;                // local unit
            int grow = g * DM + u0 + uu;      // global w_hh row
            float4 v = *reinterpret_cast<const float4*>(
                &w_hh[(size_t)grow * DM + k0 + c4]);
            swT[c4 + 0][lr] = v.x;
            swT[c4 + 1][lr] = v.y;
            swT[c4 + 2][lr] = v.z;
            swT[c4 + 3][lr] = v.w;
        }
        __syncthreads();
#pragma unroll
        for (int kk = 0; kk < KC; kk++) {
            float4 h4 = *reinterpret_cast<const float4*>(&shT[kk][tb * 4]);
            float2 wr = *reinterpret_cast<const float2*>(&swT[kk][tu * 2]);
            float2 wz = *reinterpret_cast<const float2*>(&swT[kk][16 + tu * 2]);
            float2 wn = *reinterpret_cast<const float2*>(&swT[kk][32 + tu * 2]);
            float hv[4] = {h4.x, h4.y, h4.z, h4.w};
#pragma unroll
            for (int bb = 0; bb < 4; bb++) {
                accr[bb][0] += hv[bb] * wr.x;
                accr[bb][1] += hv[bb] * wr.y;
                accz[bb][0] += hv[bb] * wz.x;
                accz[bb][1] += hv[bb] * wz.y;
                accn[bb][0] += hv[bb] * wn.x;
                accn[bb][1] += hv[bb] * wn.y;
            }
        }
        __syncthreads();
    }

    // Gates + state update
#pragma unroll
    for (int uu = 0; uu < 2; uu++) {
        int j = u0 + tu * 2 + uu;
        float bir = __ldg(&b_ih[j]),            bhr = __ldg(&b_hh[j]);
        float biz = __ldg(&b_ih[DM + j]),       bhz = __ldg(&b_hh[DM + j]);
        float bin = __ldg(&b_ih[2 * DM + j]),   bhn = __ldg(&b_hh[2 * DM + j]);
#pragma unroll
        for (int bb = 0; bb < 4; bb++) {
            int b = b0 + tb * 4 + bb;
            float r  = 1.f / (1.f + expf(-(bir + bhr + accr[bb][uu])));
            float zg = 1.f / (1.f + expf(-(biz + bhz + accz[bb][uu])));
            float n  = tanhf(bin + r * (bhn + accn[bb][uu]));
            float hp = hprev[(size_t)b * DM + j];
            hnext[(size_t)b * DM + j] = (1.f - zg) * n + zg * hp;
        }
    }
}

// ---------------------------------------------------------------------------
// out[b,t,:] = hs[t+1][b,:] @ out_w.T + out_b
// Rows R = t*256 + b (matches g_hs layout, slot shifted by +1).
// Block: 64 rows x 64 cols (55 active), 256 threads, 4x4 register tile.
// ---------------------------------------------------------------------------
__global__ void __launch_bounds__(256)
out_kernel(const float* __restrict__ out_w,
           const float* __restrict__ out_b,
           float* __restrict__ out) {
    __shared__ float shH[KC][SH_STRIDE];  // [kk][row 0..63]
    __shared__ float shW[KC][SH_STRIDE];  // [kk][col 0..63] (>=55 zero-padded)
    const int R0  = blockIdx.x * 64;
    const int tid = threadIdx.x;
    const int tx  = tid & 15;   // cols 4*tx..+3
    const int ty  = tid >> 4;   // rows 4*ty..+3
    // slot 1 base: reading g_hs[(R/256)+1][R%256][:] == (g_hs + B*DM)[R*DM ..]
    const float* __restrict__ hsrc = g_hs + (size_t)BATCH * DM;

    float acc[4][4] = {};
    for (int k0 = 0; k0 < DM; k0 += KC) {
#pragma unroll
        for (int p = 0; p < 2; p++) {
            int idx = tid + 256 * p;      // 0..511
            int row = idx >> 3;
            int c4  = (idx & 7) * 4;
            float4 v = *reinterpret_cast<const float4*>(
                &hsrc[(size_t)(R0 + row) * DM + k0 + c4]);
            shH[c4 + 0][row] = v.x;
            shH[c4 + 1][row] = v.y;
            shH[c4 + 2][row] = v.z;
            shH[c4 + 3][row] = v.w;
        }
#pragma unroll
        for (int p = 0; p < 2; p++) {
            int idx = tid + 256 * p;      // 0..511
            int i   = idx >> 3;           // 0..63
            int c4  = (idx & 7) * 4;
            float4 v = make_float4(0.f, 0.f, 0.f, 0.f);
            if (i < ENC)
                v = *reinterpret_cast<const float4*>(
                    &out_w[(size_t)i * DM + k0 + c4]);
            shW[c4 + 0][i] = v.x;
            shW[c4 + 1][i] = v.y;
            shW[c4 + 2][i] = v.z;
            shW[c4 + 3][i] = v.w;
        }
        __syncthreads();
#pragma unroll
        for (int kk = 0; kk < KC; kk++) {
            float4 hv = *reinterpret_cast<const float4*>(&shH[kk][ty * 4]);
            float4 wv = *reinterpret_cast<const float4*>(&shW[kk][tx * 4]);
            float h[4] = {hv.x, hv.y, hv.z, hv.w};
            float w[4] = {wv.x, wv.y, wv.z, wv.w};
#pragma unroll
            for (int rr = 0; rr < 4; rr++)
#pragma unroll
                for (int cc = 0; cc < 4; cc++)
                    acc[rr][cc] += h[rr] * w[cc];
        }
        __syncthreads();
    }
#pragma unroll
    for (int rr = 0; rr < 4; rr++) {
        int R  = R0 + ty * 4 + rr;
        int tt = R >> 8;      // timestep
        int b  = R & 255;     // batch
#pragma unroll
        for (int cc = 0; cc < 4; cc++) {
            int i = tx * 4 + cc;
            if (i < ENC)
                out[((size_t)b * WIN + tt) * ENC + i] = acc[rr][cc] + __ldg(&out_b[i]);
        }
    }
}

// ---------------------------------------------------------------------------
// Inputs (metadata order): 0 z, 1 h_proj_w, 2 h_proj_b, 3 w_ih (unused),
// 4 w_hh, 5 b_ih, 6 b_hh, 7 out_w, 8 out_b, 9 win_size (compile-time 256)
// ---------------------------------------------------------------------------
extern "C" void kernel_launch(void* const* d_in, const int* in_sizes, int n_in,
                              void* d_out, int out_size) {
    (void)in_sizes; (void)n_in; (void)out_size;
    const float* z        = (const float*)d_in[0];
    const float* h_proj_w = (const float*)d_in[1];
    const float* h_proj_b = (const float*)d_in[2];
    const float* w_hh     = (const float*)d_in[4];
    const float* b_ih     = (const float*)d_in[5];
    const float* b_hh     = (const float*)d_in[6];
    const float* out_w    = (const float*)d_in[7];
    const float* out_b    = (const float*)d_in[8];
    float* out = (float*)d_out;

    h0_kernel<<<BATCH, DM>>>(z, h_proj_w, h_proj_b);
    for (int t = 0; t < WIN; t++)
        step_kernel<<<dim3(DM / 16, BATCH / 64), 128>>>(w_hh, b_ih, b_hh, t);
    out_kernel<<<(WIN * BATCH) / 64, 256>>>(out_w, out_b, out);
}

// round 4
// speedup vs baseline: 3.0830x; 3.0830x over previous
#include <cuda_runtime.h>
#include <cuda_bf16.h>
#include <cstdint>
#include <math.h>

#define DM     512
#define BATCH  256
#define WIN    256
#define ENC    55
#define LATENT 128
#define BS     (BATCH * DM)

// ---------------- global scratch ----------------
__device__ float g_hs[(WIN + 1) * BS];            // fp32 hidden history
__device__ __nv_bfloat16 g_hhi[2][BS];            // h split hi (ping-pong)
__device__ __nv_bfloat16 g_hlo[2][BS];            // h split lo
__device__ __nv_bfloat16 g_whi[3 * DM * DM];      // w_hh split hi
__device__ __nv_bfloat16 g_wlo[3 * DM * DM];      // w_hh split lo
__device__ unsigned g_bar = 0;                    // grid barrier counter

// ---------------- PTX helpers ----------------
__device__ __forceinline__ uint32_t smem_u32(const void* p) {
    uint32_t a;
    asm("{ .reg .u64 t; cvta.to.shared.u64 t, %1; cvt.u32.u64 %0, t; }" : "=r"(a) : "l"(p));
    return a;
}
__device__ __forceinline__ void cp16(uint32_t dst, const void* src) {
    asm volatile("cp.async.cg.shared.global [%0], [%1], 16;" :: "r"(dst), "l"(src));
}
#define CP_COMMIT() asm volatile("cp.async.commit_group;" ::: "memory")
template <int N> __device__ __forceinline__ void cp_wait() {
    asm volatile("cp.async.wait_group %0;" :: "n"(N) : "memory");
}
__device__ __forceinline__ void ldsm_x4(uint32_t r[4], uint32_t addr) {
    asm volatile("ldmatrix.sync.aligned.m8n8.x4.shared.b16 {%0,%1,%2,%3}, [%4];"
                 : "=r"(r[0]), "=r"(r[1]), "=r"(r[2]), "=r"(r[3]) : "r"(addr));
}
__device__ __forceinline__ void ldsm_x2(uint32_t r[2], uint32_t addr) {
    asm volatile("ldmatrix.sync.aligned.m8n8.x2.shared.b16 {%0,%1}, [%2];"
                 : "=r"(r[0]), "=r"(r[1]) : "r"(addr));
}
__device__ __forceinline__ void mma_bf16(float c[4], const uint32_t a[4], const uint32_t b[2]) {
    asm volatile("mma.sync.aligned.m16n8k16.row.col.f32.bf16.bf16.f32 "
                 "{%0,%1,%2,%3}, {%4,%5,%6,%7}, {%8,%9}, {%0,%1,%2,%3};"
                 : "+f"(c[0]), "+f"(c[1]), "+f"(c[2]), "+f"(c[3])
                 : "r"(a[0]), "r"(a[1]), "r"(a[2]), "r"(a[3]), "r"(b[0]), "r"(b[1]));
}

// ---------------- persistent step kernel config ----------------
#define NCTA     128
#define UT       16                   // units per CTA
#define MT       64                   // batch rows per CTA
#define WROW_B   1040                 // W smem row stride bytes (520 bf16)
#define AROW_B   272                  // A smem row stride bytes (136 bf16)
#define KC       128                  // K chunk (elems)
#define WHI_OFF  0
#define WLO_OFF  49920                // 48*1040
#define ABUF_OFF 99840
#define ABUF_SZ  17408                // 64*272
#define AHI_OFF(buf) (ABUF_OFF + (buf) * (2 * ABUF_SZ))
#define ALO_OFF(buf) (AHI_OFF(buf) + ABUF_SZ)
#define DYN_BYTES (ABUF_OFF + 4 * ABUF_SZ)   // 169472
#define GEX_STRIDE 52

__device__ __forceinline__ void loadA(uint32_t dstHi, uint32_t dstLo,
                                      const __nv_bfloat16* __restrict__ hi,
                                      const __nv_bfloat16* __restrict__ lo,
                                      int b0, int kc, int tid) {
#pragma unroll
    for (int p = 0; p < 8; p++) {
        int idx = tid + 128 * p;
        int row = idx >> 4, c16 = idx & 15;
        cp16(dstHi + row * AROW_B + c16 * 16,
             hi + (size_t)(b0 + row) * DM + kc + c16 * 8);
    }
#pragma unroll
    for (int p = 0; p < 8; p++) {
        int idx = tid + 128 * p;
        int row = idx >> 4, c16 = idx & 15;
        cp16(dstLo + row * AROW_B + c16 * 16,
             lo + (size_t)(b0 + row) * DM + kc + c16 * 8);
    }
}

__global__ void __launch_bounds__(128, 1)
gru_persistent(const float* __restrict__ b_ih, const float* __restrict__ b_hh) {
    extern __shared__ char dyn[];
    __shared__ float s_sr[UT], s_sz[UT], s_bin[UT], s_bhn[UT];

    const int tid = threadIdx.x;
    const int lane = tid & 31;
    const int warp = tid >> 5;
    const int warp_m = warp >> 1;     // 0..1 -> 32 rows each
    const int warp_n = warp & 1;      // 0..1 -> 24 cols each
    const int cta = blockIdx.x;
    const int u0 = (cta & 31) * UT;
    const int b0 = (cta >> 5) * MT;
    const uint32_t sb = smem_u32(dyn);
    float* gex = reinterpret_cast<float*>(dyn + ABUF_OFF);

    // ---- load weight tiles into resident smem (once) ----
    for (int idx = tid; idx < 48 * 64; idx += 128) {
        int n = idx >> 6, c8 = idx & 63;              // row n, 16B unit c8
        int gr = (n >> 4) * DM + u0 + (n & 15);       // w_hh global row
        *reinterpret_cast<uint4*>(dyn + WHI_OFF + n * WROW_B + c8 * 16) =
            *reinterpret_cast<const uint4*>(g_whi + (size_t)gr * DM + c8 * 8);
        *reinterpret_cast<uint4*>(dyn + WLO_OFF + n * WROW_B + c8 * 16) =
            *reinterpret_cast<const uint4*>(g_wlo + (size_t)gr * DM + c8 * 8);
    }
    if (tid < UT) {
        int j = u0 + tid;
        s_sr[tid]  = b_ih[j] + b_hh[j];
        s_sz[tid]  = b_ih[DM + j] + b_hh[DM + j];
        s_bin[tid] = b_ih[2 * DM + j];
        s_bhn[tid] = b_hh[2 * DM + j];
    }
    __syncthreads();

    // per-thread fragment address offsets
    const int m_base = warp_m * 32;
    const int n_base = warp_n * 24;
    const uint32_t a_off = (uint32_t)(((lane & 7) + ((lane >> 3) & 1) * 8) * AROW_B
                                      + ((lane >> 4) & 1) * 16);
    const uint32_t b_off = (uint32_t)((n_base + (lane & 7)) * WROW_B
                                      + ((lane >> 3) & 1) * 16);
    const uint32_t wh_base = sb + WHI_OFF + b_off;
    const uint32_t wl_base = sb + WLO_OFF + b_off;

    for (int t = 0; t < WIN; t++) {
        const __nv_bfloat16* __restrict__ hsel = g_hhi[t & 1];
        const __nv_bfloat16* __restrict__ lsel = g_hlo[t & 1];

        loadA(sb + AHI_OFF(0), sb + ALO_OFF(0), hsel, lsel, b0, 0, tid);
        CP_COMMIT();

        float cf[2][3][4];
#pragma unroll
        for (int mi = 0; mi < 2; mi++)
#pragma unroll
            for (int ni = 0; ni < 3; ni++)
#pragma unroll
                for (int q = 0; q < 4; q++) cf[mi][ni][q] = 0.f;

        for (int ch = 0; ch < 4; ch++) {
            if (ch < 3) {
                loadA(sb + AHI_OFF((ch + 1) & 1), sb + ALO_OFF((ch + 1) & 1),
                      hsel, lsel, b0, (ch + 1) * KC, tid);
                CP_COMMIT();
                cp_wait<1>();
            } else {
                cp_wait<0>();
            }
            __syncthreads();

            const uint32_t ah_base = sb + AHI_OFF(ch & 1) + m_base * AROW_B + a_off;
            const uint32_t al_base = ah_base + ABUF_SZ;
#pragma unroll
            for (int k16 = 0; k16 < 8; k16++) {
                const uint32_t ka = ah_base + k16 * 32;
                const uint32_t kl = al_base + k16 * 32;
                uint32_t ah0[4], ah1[4], al0[4], al1[4];
                ldsm_x4(ah0, ka);
                ldsm_x4(ah1, ka + 16 * AROW_B);
                ldsm_x4(al0, kl);
                ldsm_x4(al1, kl + 16 * AROW_B);
                const uint32_t kg2 = (uint32_t)((ch * KC + k16 * 16) * 2);
                uint32_t bhf[3][2], blf[3][2];
#pragma unroll
                for (int ni = 0; ni < 3; ni++) {
                    ldsm_x2(bhf[ni], wh_base + ni * 8 * WROW_B + kg2);
                    ldsm_x2(blf[ni], wl_base + ni * 8 * WROW_B + kg2);
                }
#pragma unroll
                for (int ni = 0; ni < 3; ni++) {
                    mma_bf16(cf[0][ni], ah0, bhf[ni]);
                    mma_bf16(cf[1][ni], ah1, bhf[ni]);
                    mma_bf16(cf[0][ni], ah0, blf[ni]);
                    mma_bf16(cf[1][ni], ah1, blf[ni]);
                    mma_bf16(cf[0][ni], al0, bhf[ni]);
                    mma_bf16(cf[1][ni], al1, bhf[ni]);
                }
            }
            __syncthreads();
        }

        // ---- epilogue: exchange C through smem, fuse gates ----
#pragma unroll
        for (int mi = 0; mi < 2; mi++)
#pragma unroll
            for (int ni = 0; ni < 3; ni++) {
                int r0 = m_base + mi * 16 + (lane >> 2);
                int c0 = n_base + ni * 8 + (lane & 3) * 2;
                *reinterpret_cast<float2*>(&gex[r0 * GEX_STRIDE + c0]) =
                    make_float2(cf[mi][ni][0], cf[mi][ni][1]);
                *reinterpret_cast<float2*>(&gex[(r0 + 8) * GEX_STRIDE + c0]) =
                    make_float2(cf[mi][ni][2], cf[mi][ni][3]);
            }
        __syncthreads();

        {
            const int b_l = tid >> 1;
            const int uh = (tid & 1) * 8;
            const int b = b0 + b_l;
            const float* __restrict__ hp = g_hs + (size_t)t * BS + (size_t)b * DM + u0 + uh;
            float* __restrict__ hn = g_hs + (size_t)(t + 1) * BS + (size_t)b * DM + u0 + uh;
            __nv_bfloat16* __restrict__ oh = g_hhi[(t + 1) & 1] + (size_t)b * DM + u0 + uh;
            __nv_bfloat16* __restrict__ ol = g_hlo[(t + 1) & 1] + (size_t)b * DM + u0 + uh;
#pragma unroll
            for (int uu = 0; uu < 8; uu++) {
                int u = uh + uu;
                float gr = gex[b_l * GEX_STRIDE + u];
                float gz = gex[b_l * GEX_STRIDE + 16 + u];
                float gn = gex[b_l * GEX_STRIDE + 32 + u];
                float r  = 1.f / (1.f + expf(-(s_sr[u] + gr)));
                float zg = 1.f / (1.f + expf(-(s_sz[u] + gz)));
                float n  = tanhf(s_bin[u] + r * (s_bhn[u] + gn));
                float h  = (1.f - zg) * n + zg * hp[uu];
                hn[uu] = h;
                __nv_bfloat16 hi = __float2bfloat16(h);
                oh[uu] = hi;
                ol[uu] = __float2bfloat16(h - __bfloat162float(hi));
            }
        }
        __threadfence();
        __syncthreads();

        // ---- grid barrier (monotonic counter; reset by h0 each launch) ----
        if (tid == 0) {
            atomicAdd(&g_bar, 1u);
            const unsigned tgt = (unsigned)NCTA * (unsigned)(t + 1);
            while (atomicAdd(&g_bar, 0u) < tgt) __nanosleep(64);
        }
        __syncthreads();
        __threadfence();
    }
}

// ---------------- weight split prep ----------------
__global__ void prep_kernel(const float* __restrict__ w) {
    int i = blockIdx.x * blockDim.x + threadIdx.x;
    if (i < 3 * DM * DM) {
        float v = w[i];
        __nv_bfloat16 hi = __float2bfloat16(v);
        g_whi[i] = hi;
        g_wlo[i] = __float2bfloat16(v - __bfloat162float(hi));
    }
}

// ---------------- h0 ----------------
__global__ void h0_kernel(const float* __restrict__ z,
                          const float* __restrict__ w,
                          const float* __restrict__ bias) {
    __shared__ float zs[LATENT];
    const int b = blockIdx.x;
    const int j = threadIdx.x;
    if (b == 0 && j == 0) g_bar = 0;   // reset grid barrier every replay
    if (threadIdx.x < LATENT) zs[threadIdx.x] = z[b * LATENT + threadIdx.x];
    __syncthreads();
    float acc = 0.f;
    const float4* wr = reinterpret_cast<const float4*>(w + (size_t)j * LATENT);
#pragma unroll
    for (int k4 = 0; k4 < LATENT / 4; k4++) {
        float4 w4 = __ldg(&wr[k4]);
        acc += zs[4 * k4 + 0] * w4.x + zs[4 * k4 + 1] * w4.y
             + zs[4 * k4 + 2] * w4.z + zs[4 * k4 + 3] * w4.w;
    }
    float h = tanhf(acc + bias[j]);
    g_hs[(size_t)b * DM + j] = h;
    __nv_bfloat16 hi = __float2bfloat16(h);
    g_hhi[0][(size_t)b * DM + j] = hi;
    g_hlo[0][(size_t)b * DM + j] = __float2bfloat16(h - __bfloat162float(hi));
}

// ---------------- output GEMM (fp32, proven) ----------------
#define OKC 32
#define OST 68
__global__ void __launch_bounds__(256)
out_kernel(const float* __restrict__ out_w,
           const float* __restrict__ out_b,
           float* __restrict__ out) {
    __shared__ float shH[OKC][OST];
    __shared__ float shW[OKC][OST];
    const int R0  = blockIdx.x * 64;
    const int tid = threadIdx.x;
    const int tx  = tid & 15;
    const int ty  = tid >> 4;
    const float* __restrict__ hsrc = g_hs + (size_t)BS;

    float acc[4][4] = {};
    for (int k0 = 0; k0 < DM; k0 += OKC) {
#pragma unroll
        for (int p = 0; p < 2; p++) {
            int idx = tid + 256 * p;
            int row = idx >> 3;
            int c4  = (idx & 7) * 4;
            float4 v = *reinterpret_cast<const float4*>(
                &hsrc[(size_t)(R0 + row) * DM + k0 + c4]);
            shH[c4 + 0][row] = v.x; shH[c4 + 1][row] = v.y;
            shH[c4 + 2][row] = v.z; shH[c4 + 3][row] = v.w;
        }
#pragma unroll
        for (int p = 0; p < 2; p++) {
            int idx = tid + 256 * p;
            int i   = idx >> 3;
            int c4  = (idx & 7) * 4;
            float4 v = make_float4(0.f, 0.f, 0.f, 0.f);
            if (i < ENC)
                v = *reinterpret_cast<const float4*>(&out_w[(size_t)i * DM + k0 + c4]);
            shW[c4 + 0][i] = v.x; shW[c4 + 1][i] = v.y;
            shW[c4 + 2][i] = v.z; shW[c4 + 3][i] = v.w;
        }
        __syncthreads();
#pragma unroll
        for (int kk = 0; kk < OKC; kk++) {
            float4 hv = *reinterpret_cast<const float4*>(&shH[kk][ty * 4]);
            float4 wv = *reinterpret_cast<const float4*>(&shW[kk][tx * 4]);
            float h[4] = {hv.x, hv.y, hv.z, hv.w};
            float w[4] = {wv.x, wv.y, wv.z, wv.w};
#pragma unroll
            for (int rr = 0; rr < 4; rr++)
#pragma unroll
                for (int cc = 0; cc < 4; cc++)
                    acc[rr][cc] += h[rr] * w[cc];
        }
        __syncthreads();
    }
#pragma unroll
    for (int rr = 0; rr < 4; rr++) {
        int R  = R0 + ty * 4 + rr;
        int tt = R >> 8;
        int b  = R & 255;
#pragma unroll
        for (int cc = 0; cc < 4; cc++) {
            int i = tx * 4 + cc;
            if (i < ENC)
                out[((size_t)b * WIN + tt) * ENC + i] = acc[rr][cc] + __ldg(&out_b[i]);
        }
    }
}

// ---------------- launch ----------------
extern "C" void kernel_launch(void* const* d_in, const int* in_sizes, int n_in,
                              void* d_out, int out_size) {
    (void)in_sizes; (void)n_in; (void)out_size;
    const float* z        = (const float*)d_in[0];
    const float* h_proj_w = (const float*)d_in[1];
    const float* h_proj_b = (const float*)d_in[2];
    const float* w_hh     = (const float*)d_in[4];
    const float* b_ih     = (const float*)d_in[5];
    const float* b_hh     = (const float*)d_in[6];
    const float* out_w    = (const float*)d_in[7];
    const float* out_b    = (const float*)d_in[8];
    float* out = (float*)d_out;

    static bool attr_done = false;
    if (!attr_done) {
        cudaFuncSetAttribute(gru_persistent,
                             cudaFuncAttributeMaxDynamicSharedMemorySize, DYN_BYTES);
        attr_done = true;
    }

    prep_kernel<<<(3 * DM * DM + 255) / 256, 256>>>(w_hh);
    h0_kernel<<<BATCH, DM>>>(z, h_proj_w, h_proj_b);
    gru_persistent<<<NCTA, 128, DYN_BYTES>>>(b_ih, b_hh);
    out_kernel<<<(WIN * BATCH) / 64, 256>>>(out_w, out_b, out);
}

// round 5
// speedup vs baseline: 3.2527x; 1.0550x over previous
#include <cuda_runtime.h>
#include <cuda_bf16.h>
#include <cstdint>
#include <math.h>

#define DM     512
#define BATCH  256
#define WIN    256
#define ENC    55
#define LATENT 128
#define BS     (BATCH * DM)

// ---------------- global scratch ----------------
__device__ float g_hs[(WIN + 1) * BS];            // fp32 hidden history
__device__ __nv_bfloat16 g_hhi[2][BS];            // h split hi (ping-pong)
__device__ __nv_bfloat16 g_hlo[2][BS];            // h split lo
__device__ __nv_bfloat16 g_whi[3 * DM * DM];      // w_hh split hi
__device__ __nv_bfloat16 g_wlo[3 * DM * DM];      // w_hh split lo
__device__ unsigned g_bar = 0;                    // arrival counter
__device__ volatile unsigned g_flag = 0;          // release flag (step id)

// ---------------- PTX helpers ----------------
__device__ __forceinline__ uint32_t smem_u32(const void* p) {
    uint32_t a;
    asm("{ .reg .u64 t; cvta.to.shared.u64 t, %1; cvt.u32.u64 %0, t; }" : "=r"(a) : "l"(p));
    return a;
}
__device__ __forceinline__ void cp16(uint32_t dst, const void* src) {
    asm volatile("cp.async.cg.shared.global [%0], [%1], 16;" :: "r"(dst), "l"(src));
}
#define CP_COMMIT() asm volatile("cp.async.commit_group;" ::: "memory")
template <int N> __device__ __forceinline__ void cp_wait() {
    asm volatile("cp.async.wait_group %0;" :: "n"(N) : "memory");
}
__device__ __forceinline__ void ldsm_x4(uint32_t r[4], uint32_t addr) {
    asm volatile("ldmatrix.sync.aligned.m8n8.x4.shared.b16 {%0,%1,%2,%3}, [%4];"
                 : "=r"(r[0]), "=r"(r[1]), "=r"(r[2]), "=r"(r[3]) : "r"(addr));
}
__device__ __forceinline__ void ldsm_x2(uint32_t r[2], uint32_t addr) {
    asm volatile("ldmatrix.sync.aligned.m8n8.x2.shared.b16 {%0,%1}, [%2];"
                 : "=r"(r[0]), "=r"(r[1]) : "r"(addr));
}
__device__ __forceinline__ void mma_bf16(float c[4], const uint32_t a[4], const uint32_t b[2]) {
    asm volatile("mma.sync.aligned.m16n8k16.row.col.f32.bf16.bf16.f32 "
                 "{%0,%1,%2,%3}, {%4,%5,%6,%7}, {%8,%9}, {%0,%1,%2,%3};"
                 : "+f"(c[0]), "+f"(c[1]), "+f"(c[2]), "+f"(c[3])
                 : "r"(a[0]), "r"(a[1]), "r"(a[2]), "r"(a[3]), "r"(b[0]), "r"(b[1]));
}

// ---------------- persistent step kernel config ----------------
#define NCTA     128
#define UT       16                   // units per CTA
#define MT       64                   // batch rows per CTA
#define WROW_B   1040                 // W smem row stride bytes
#define AROW_B   272                  // A smem row stride bytes
#define KC       128                  // K chunk (elems)
#define WHI_OFF  0
#define WLO_OFF  49920                // 48*1040
#define ABUF_OFF 99840
#define ABUF_SZ  17408                // 64*272
#define ABUF(i)  (ABUF_OFF + (i) * (2 * ABUF_SZ))
#define DYN_BYTES (ABUF_OFF + 3 * 2 * ABUF_SZ)   // 204288
#define GEX_STRIDE 52

__device__ __forceinline__ void loadA(uint32_t dstHi,
                                      const __nv_bfloat16* __restrict__ hi,
                                      const __nv_bfloat16* __restrict__ lo,
                                      int b0, int kc, int tid) {
#pragma unroll
    for (int p = 0; p < 4; p++) {
        int idx = tid + 256 * p;
        int row = idx >> 4, c16 = idx & 15;
        cp16(dstHi + row * AROW_B + c16 * 16,
             hi + (size_t)(b0 + row) * DM + kc + c16 * 8);
    }
#pragma unroll
    for (int p = 0; p < 4; p++) {
        int idx = tid + 256 * p;
        int row = idx >> 4, c16 = idx & 15;
        cp16(dstHi + ABUF_SZ + row * AROW_B + c16 * 16,
             lo + (size_t)(b0 + row) * DM + kc + c16 * 8);
    }
}

__global__ void __launch_bounds__(256, 1)
gru_persistent(const float* __restrict__ b_ih, const float* __restrict__ b_hh) {
    extern __shared__ char dyn[];
    __shared__ float gex[MT * GEX_STRIDE];
    __shared__ float s_sr[UT], s_sz[UT], s_bin[UT], s_bhn[UT];

    const int tid = threadIdx.x;
    const int lane = tid & 31;
    const int warp = tid >> 5;
    const int m_base = (warp >> 1) * 16;   // 4 M-tiles of 16 rows
    const int n_base = (warp & 1) * 24;    // 2 N-tiles of 24 cols
    const int cta = blockIdx.x;
    const int u0 = (cta & 31) * UT;
    const int b0 = (cta >> 5) * MT;
    const uint32_t sb = smem_u32(dyn);

    // ---- load resident weight tiles (once) ----
    for (int idx = tid; idx < 48 * 64; idx += 256) {
        int n = idx >> 6, c8 = idx & 63;
        int gr = (n >> 4) * DM + u0 + (n & 15);
        *reinterpret_cast<uint4*>(dyn + WHI_OFF + n * WROW_B + c8 * 16) =
            *reinterpret_cast<const uint4*>(g_whi + (size_t)gr * DM + c8 * 8);
        *reinterpret_cast<uint4*>(dyn + WLO_OFF + n * WROW_B + c8 * 16) =
            *reinterpret_cast<const uint4*>(g_wlo + (size_t)gr * DM + c8 * 8);
    }
    if (tid < UT) {
        int j = u0 + tid;
        s_sr[tid]  = b_ih[j] + b_hh[j];
        s_sz[tid]  = b_ih[DM + j] + b_hh[DM + j];
        s_bin[tid] = b_ih[2 * DM + j];
        s_bhn[tid] = b_hh[2 * DM + j];
    }
    __syncthreads();

    const uint32_t a_off = (uint32_t)(((lane & 7) + ((lane >> 3) & 1) * 8) * AROW_B
                                      + ((lane >> 4) & 1) * 16);
    const uint32_t b_off = (uint32_t)((n_base + (lane & 7)) * WROW_B
                                      + ((lane >> 3) & 1) * 16);
    const uint32_t wh_base = sb + WHI_OFF + b_off;
    const uint32_t wl_base = sb + WLO_OFF + b_off;

    for (int t = 0; t < WIN; t++) {
        const __nv_bfloat16* __restrict__ hsel = g_hhi[t & 1];
        const __nv_bfloat16* __restrict__ lsel = g_hlo[t & 1];

        loadA(sb + ABUF(0), hsel, lsel, b0, 0, tid);
        CP_COMMIT();

        float cf[3][4];
#pragma unroll
        for (int ni = 0; ni < 3; ni++)
#pragma unroll
            for (int q = 0; q < 4; q++) cf[ni][q] = 0.f;

#pragma unroll
        for (int ch = 0; ch < 4; ch++) {
            if (ch < 3) {
                loadA(sb + ABUF((ch + 1) % 3), hsel, lsel, b0, (ch + 1) * KC, tid);
                CP_COMMIT();
                cp_wait<1>();
            } else {
                cp_wait<0>();
            }
            __syncthreads();

            const uint32_t ah_base = sb + ABUF(ch % 3) + m_base * AROW_B + a_off;
            const uint32_t al_base = ah_base + ABUF_SZ;
#pragma unroll
            for (int k16 = 0; k16 < 8; k16++) {
                uint32_t ah[4], al[4];
                ldsm_x4(ah, ah_base + k16 * 32);
                ldsm_x4(al, al_base + k16 * 32);
                const uint32_t kg2 = (uint32_t)((ch * KC + k16 * 16) * 2);
                uint32_t bhf[3][2], blf[3][2];
#pragma unroll
                for (int ni = 0; ni < 3; ni++) {
                    ldsm_x2(bhf[ni], wh_base + ni * 8 * WROW_B + kg2);
                    ldsm_x2(blf[ni], wl_base + ni * 8 * WROW_B + kg2);
                }
#pragma unroll
                for (int ni = 0; ni < 3; ni++) {
                    mma_bf16(cf[ni], ah, bhf[ni]);
                    mma_bf16(cf[ni], ah, blf[ni]);
                    mma_bf16(cf[ni], al, bhf[ni]);
                }
            }
        }

        // ---- epilogue: exchange C through smem, fuse gates ----
#pragma unroll
        for (int ni = 0; ni < 3; ni++) {
            int r0 = m_base + (lane >> 2);
            int c0 = n_base + ni * 8 + (lane & 3) * 2;
            *reinterpret_cast<float2*>(&gex[r0 * GEX_STRIDE + c0]) =
                make_float2(cf[ni][0], cf[ni][1]);
            *reinterpret_cast<float2*>(&gex[(r0 + 8) * GEX_STRIDE + c0]) =
                make_float2(cf[ni][2], cf[ni][3]);
        }
        __syncthreads();

        {
            const int b_l = tid >> 2;           // 0..63
            const int uh = (tid & 3) * 4;       // 4 units each
            const int b = b0 + b_l;
            const float* __restrict__ hp = g_hs + (size_t)t * BS + (size_t)b * DM + u0 + uh;
            float* __restrict__ hn = g_hs + (size_t)(t + 1) * BS + (size_t)b * DM + u0 + uh;
            __nv_bfloat16* __restrict__ oh = g_hhi[(t + 1) & 1] + (size_t)b * DM + u0 + uh;
            __nv_bfloat16* __restrict__ ol = g_hlo[(t + 1) & 1] + (size_t)b * DM + u0 + uh;
#pragma unroll
            for (int uu = 0; uu < 4; uu++) {
                int u = uh + uu;
                float gr = gex[b_l * GEX_STRIDE + u];
                float gz = gex[b_l * GEX_STRIDE + 16 + u];
                float gn = gex[b_l * GEX_STRIDE + 32 + u];
                float r  = 1.f / (1.f + expf(-(s_sr[u] + gr)));
                float zg = 1.f / (1.f + expf(-(s_sz[u] + gz)));
                float n  = tanhf(s_bin[u] + r * (s_bhn[u] + gn));
                float h  = (1.f - zg) * n + zg * hp[uu];
                hn[uu] = h;
                __nv_bfloat16 hi = __float2bfloat16(h);
                oh[uu] = hi;
                ol[uu] = __float2bfloat16(h - __bfloat162float(hi));
            }
        }
        __threadfence();
        __syncthreads();

        // ---- grid barrier: atomic arrive + flag release + load-poll ----
        if (tid == 0) {
            const unsigned tgt = (unsigned)NCTA * (unsigned)(t + 1);
            unsigned old = atomicAdd(&g_bar, 1u);
            if (old == tgt - 1u) {
                __threadfence();
                g_flag = tgt;
            } else {
                while (g_flag < tgt) { }
            }
        }
        __syncthreads();
    }
}

// ---------------- weight split prep ----------------
__global__ void prep_kernel(const float* __restrict__ w) {
    int i = blockIdx.x * blockDim.x + threadIdx.x;
    if (i < 3 * DM * DM) {
        float v = w[i];
        __nv_bfloat16 hi = __float2bfloat16(v);
        g_whi[i] = hi;
        g_wlo[i] = __float2bfloat16(v - __bfloat162float(hi));
    }
}

// ---------------- h0 ----------------
__global__ void h0_kernel(const float* __restrict__ z,
                          const float* __restrict__ w,
                          const float* __restrict__ bias) {
    __shared__ float zs[LATENT];
    const int b = blockIdx.x;
    const int j = threadIdx.x;
    if (b == 0 && j == 0) { g_bar = 0; g_flag = 0; }   // reset barrier每 replay
    if (threadIdx.x < LATENT) zs[threadIdx.x] = z[b * LATENT + threadIdx.x];
    __syncthreads();
    float acc = 0.f;
    const float4* wr = reinterpret_cast<const float4*>(w + (size_t)j * LATENT);
#pragma unroll
    for (int k4 = 0; k4 < LATENT / 4; k4++) {
        float4 w4 = __ldg(&wr[k4]);
        acc += zs[4 * k4 + 0] * w4.x + zs[4 * k4 + 1] * w4.y
             + zs[4 * k4 + 2] * w4.z + zs[4 * k4 + 3] * w4.w;
    }
    float h = tanhf(acc + bias[j]);
    g_hs[(size_t)b * DM + j] = h;
    __nv_bfloat16 hi = __float2bfloat16(h);
    g_hhi[0][(size_t)b * DM + j] = hi;
    g_hlo[0][(size_t)b * DM + j] = __float2bfloat16(h - __bfloat162float(hi));
}

// ---------------- output GEMM: 128x64 tile, 8x4 per thread ----------------
#define OKC 32
__global__ void __launch_bounds__(256)
out_kernel(const float* __restrict__ out_w,
           const float* __restrict__ out_b,
           float* __restrict__ out) {
    __shared__ float shH[OKC][132];
    __shared__ float shW[OKC][68];
    const int R0  = blockIdx.x * 128;
    const int tid = threadIdx.x;
    const int tx  = tid & 15;   // cols 4*tx..+3
    const int ty  = tid >> 4;   // rows 8*ty..+7
    const float* __restrict__ hsrc = g_hs + (size_t)BS;

    float acc[8][4] = {};
    for (int k0 = 0; k0 < DM; k0 += OKC) {
#pragma unroll
        for (int p = 0; p < 4; p++) {
            int idx = tid + 256 * p;      // 0..1023
            int row = idx >> 3;
            int c4  = (idx & 7) * 4;
            float4 v = *reinterpret_cast<const float4*>(
                &hsrc[(size_t)(R0 + row) * DM + k0 + c4]);
            shH[c4 + 0][row] = v.x; shH[c4 + 1][row] = v.y;
            shH[c4 + 2][row] = v.z; shH[c4 + 3][row] = v.w;
        }
#pragma unroll
        for (int p = 0; p < 2; p++) {
            int idx = tid + 256 * p;      // 0..511
            int i   = idx >> 3;
            int c4  = (idx & 7) * 4;
            float4 v = make_float4(0.f, 0.f, 0.f, 0.f);
            if (i < ENC)
                v = *reinterpret_cast<const float4*>(&out_w[(size_t)i * DM + k0 + c4]);
            shW[c4 + 0][i] = v.x; shW[c4 + 1][i] = v.y;
            shW[c4 + 2][i] = v.z; shW[c4 + 3][i] = v.w;
        }
        __syncthreads();
#pragma unroll
        for (int kk = 0; kk < OKC; kk++) {
            float4 h0 = *reinterpret_cast<const float4*>(&shH[kk][ty * 8]);
            float4 h1 = *reinterpret_cast<const float4*>(&shH[kk][ty * 8 + 4]);
            float4 wv = *reinterpret_cast<const float4*>(&shW[kk][tx * 4]);
            float h[8] = {h0.x, h0.y, h0.z, h0.w, h1.x, h1.y, h1.z, h1.w};
            float w[4] = {wv.x, wv.y, wv.z, wv.w};
#pragma unroll
            for (int rr = 0; rr < 8; rr++)
#pragma unroll
                for (int cc = 0; cc < 4; cc++)
                    acc[rr][cc] += h[rr] * w[cc];
        }
        __syncthreads();
    }
#pragma unroll
    for (int rr = 0; rr < 8; rr++) {
        int R  = R0 + ty * 8 + rr;
        int tt = R >> 8;
        int b  = R & 255;
#pragma unroll
        for (int cc = 0; cc < 4; cc++) {
            int i = tx * 4 + cc;
            if (i < ENC)
                out[((size_t)b * WIN + tt) * ENC + i] = acc[rr][cc] + __ldg(&out_b[i]);
        }
    }
}

// ---------------- launch ----------------
extern "C" void kernel_launch(void* const* d_in, const int* in_sizes, int n_in,
                              void* d_out, int out_size) {
    (void)in_sizes; (void)n_in; (void)out_size;
    const float* z        = (const float*)d_in[0];
    const float* h_proj_w = (const float*)d_in[1];
    const float* h_proj_b = (const float*)d_in[2];
    const float* w_hh     = (const float*)d_in[4];
    const float* b_ih     = (const float*)d_in[5];
    const float* b_hh     = (const float*)d_in[6];
    const float* out_w    = (const float*)d_in[7];
    const float* out_b    = (const float*)d_in[8];
    float* out = (float*)d_out;

    static bool attr_done = false;
    if (!attr_done) {
        cudaFuncSetAttribute(gru_persistent,
                             cudaFuncAttributeMaxDynamicSharedMemorySize, DYN_BYTES);
        attr_done = true;
    }

    prep_kernel<<<(3 * DM * DM + 255) / 256, 256>>>(w_hh);
    h0_kernel<<<BATCH, DM>>>(z, h_proj_w, h_proj_b);
    gru_persistent<<<NCTA, 256, DYN_BYTES>>>(b_ih, b_hh);
    out_kernel<<<(WIN * BATCH) / 128, 256>>>(out_w, out_b, out);
}